// round 1
// baseline (speedup 1.0000x reference)
#include <cuda_runtime.h>

#define Nn   64
#define Cc   256
#define HWs  3136
#define Gg   16
#define CGc  16
#define Mf   200704.0f
#define EPSf 1e-3f
#define NACC 152   // 16 sums + 136 upper-tri products

// Scratch (static device globals — no allocation)
__device__ float g_part[Gg][Nn][NACC];      // per (group, n-chunk) partial stats
__device__ float g_A2[Gg][16][16][2];       // weight*wm, duplicated for f32x2
__device__ float g_beta2[Gg][16][2];        // bias - A*mean, duplicated

typedef unsigned long long u64;

__device__ __forceinline__ u64 fma2(u64 a, u64 b, u64 c) {
    u64 d;
    asm("fma.rn.f32x2 %0, %1, %2, %3;" : "=l"(d) : "l"(a), "l"(b), "l"(c));
    return d;
}

// ---------------------------------------------------------------------------
// Kernel 1: per-group channel sums + Gram matrix partials.
// Grid (16 groups, 64 batch-images), 256 threads. 152 fp32 accumulators/thread.
// ---------------------------------------------------------------------------
__global__ __launch_bounds__(256, 1) void k_stats(const float* __restrict__ X) {
    const int g = blockIdx.x, n = blockIdx.y;
    const float* base = X + ((size_t)n * Cc + (size_t)g * CGc) * HWs;

    float s[16];
    float p[136];
#pragma unroll
    for (int i = 0; i < 16; i++) s[i] = 0.f;
#pragma unroll
    for (int i = 0; i < 136; i++) p[i] = 0.f;

    for (int hw = threadIdx.x; hw < HWs; hw += 256) {
        float v[16];
#pragma unroll
        for (int c = 0; c < 16; c++) v[c] = base[c * HWs + hw];
#pragma unroll
        for (int c = 0; c < 16; c++) s[c] += v[c];
        int idx = 0;
#pragma unroll
        for (int i = 0; i < 16; i++)
#pragma unroll
            for (int j = i; j < 16; j++) { p[idx] += v[i] * v[j]; idx++; }
    }

    // intra-warp tree reduction
#pragma unroll
    for (int off = 16; off > 0; off >>= 1) {
#pragma unroll
        for (int i = 0; i < 16; i++)  s[i] += __shfl_down_sync(0xffffffffu, s[i], off);
#pragma unroll
        for (int i = 0; i < 136; i++) p[i] += __shfl_down_sync(0xffffffffu, p[i], off);
    }

    __shared__ float red[8][NACC];
    const int warp = threadIdx.x >> 5, lane = threadIdx.x & 31;
    if (lane == 0) {
#pragma unroll
        for (int i = 0; i < 16; i++)  red[warp][i]      = s[i];
#pragma unroll
        for (int i = 0; i < 136; i++) red[warp][16 + i] = p[i];
    }
    __syncthreads();
    for (int t = threadIdx.x; t < NACC; t += 256) {
        float a = 0.f;
#pragma unroll
        for (int w = 0; w < 8; w++) a += red[w][t];
        g_part[g][n][t] = a;
    }
}

// ---------------------------------------------------------------------------
// Kernel 2: reduce partials -> sigma -> Newton-Schulz Sigma^{-1/2} -> fold
// weight/bias/mean into A = w*wm and beta = b - A*mean. 16 blocks x 256 thr.
// ---------------------------------------------------------------------------
__global__ __launch_bounds__(256, 1) void k_wm(const float* __restrict__ wgt,
                                               const float* __restrict__ bia) {
    const int g = blockIdx.x;
    const int t = threadIdx.x;

    __shared__ float S[NACC];
    __shared__ float meanS[16];
    __shared__ float sig[16][17], P[16][17], T1[16][17], T2[16][17];

    if (t < NACC) {
        float a = 0.f;
        for (int ch = 0; ch < Nn; ch++) a += g_part[g][ch][t];
        S[t] = a;
    }
    __syncthreads();
    if (t < 16) meanS[t] = S[t] * (1.0f / Mf);
    __syncthreads();

    const int r = t >> 4, c = t & 15;
    const int i = (r < c) ? r : c;
    const int j = (r < c) ? c : r;
    const int pidx = 16 + i * 16 - (i * (i - 1)) / 2 + (j - i);
    float sv = S[pidx] * (1.0f / Mf) - meanS[r] * meanS[c] + ((r == c) ? EPSf : 0.f);
    sig[r][c] = sv;
    __syncthreads();

    float tr = 0.f;
#pragma unroll
    for (int k = 0; k < 16; k++) tr += sig[k][k];
    __syncthreads();

    sig[r][c] = sv / tr;                 // Sigma_N
    P[r][c] = (r == c) ? 1.f : 0.f;
    __syncthreads();

    for (int it = 0; it < 10; it++) {
        float d1 = 0.f;
#pragma unroll
        for (int k = 0; k < 16; k++) d1 += P[r][k] * P[k][c];
        T1[r][c] = d1;
        __syncthreads();
        float d2 = 0.f;
#pragma unroll
        for (int k = 0; k < 16; k++) d2 += T1[r][k] * P[k][c];
        T2[r][c] = d2;
        __syncthreads();
        float d3 = 0.f;
#pragma unroll
        for (int k = 0; k < 16; k++) d3 += T2[r][k] * sig[k][c];
        P[r][c] = 1.5f * P[r][c] - 0.5f * d3;   // own element only
        __syncthreads();
    }

    const float wmv = P[r][c] * rsqrtf(tr);      // Sigma^{-1/2}
    const float Av  = wgt[g * 16 + r] * wmv;
    g_A2[g][r][c][0] = Av;
    g_A2[g][r][c][1] = Av;
    T1[r][c] = Av * meanS[c];
    __syncthreads();
    if (t < 16) {
        float acc = bia[g * 16 + t];
#pragma unroll
        for (int d = 0; d < 16; d++) acc -= T1[t][d];
        g_beta2[g][t][0] = acc;
        g_beta2[g][t][1] = acc;
    }
}

// ---------------------------------------------------------------------------
// Kernel 3: apply out = A*v + beta with packed f32x2 FMA, 4 positions/thread.
// Grid (16 groups, 64 images), 256 threads.
// ---------------------------------------------------------------------------
__global__ __launch_bounds__(256, 2) void k_apply(const float* __restrict__ X,
                                                  float* __restrict__ Y) {
    const int g = blockIdx.x, n = blockIdx.y;
    const int t = threadIdx.x;

    __shared__ u64 As[256];
    __shared__ u64 Bs[16];
    As[t] = ((const u64*)g_A2)[g * 256 + t];
    if (t < 16) Bs[t] = ((const u64*)g_beta2)[g * 16 + t];
    __syncthreads();

    const size_t off = ((size_t)n * Cc + (size_t)g * CGc) * HWs;
    const u64* xb = (const u64*)(X + off);
    u64*       yb = (u64*)(Y + off);
    const int HW2 = HWs / 2;   // 1568 float2 per channel

    for (int q = 2 * t; q < HW2; q += 512) {
        u64 vlo[16], vhi[16];
#pragma unroll
        for (int d = 0; d < 16; d++) {
            vlo[d] = xb[d * HW2 + q];
            vhi[d] = xb[d * HW2 + q + 1];
        }
#pragma unroll
        for (int c = 0; c < 16; c++) {
            u64 a0 = Bs[c], a1 = Bs[c];
#pragma unroll
            for (int d = 0; d < 16; d++) {
                const u64 w = As[c * 16 + d];
                a0 = fma2(w, vlo[d], a0);
                a1 = fma2(w, vhi[d], a1);
            }
            yb[c * HW2 + q]     = a0;
            yb[c * HW2 + q + 1] = a1;
        }
    }
}

// ---------------------------------------------------------------------------
extern "C" void kernel_launch(void* const* d_in, const int* in_sizes, int n_in,
                              void* d_out, int out_size) {
    const float* X = (const float*)d_in[0];
    const float* W = (const float*)d_in[1];
    const float* B = (const float*)d_in[2];
    float* Y = (float*)d_out;

    dim3 grid(Gg, Nn);
    k_stats<<<grid, 256>>>(X);
    k_wm<<<Gg, 256>>>(W, B);
    k_apply<<<grid, 256>>>(X, Y);
}

// round 2
// speedup vs baseline: 1.7343x; 1.7343x over previous
#include <cuda_runtime.h>

#define Nn   64
#define Cc   256
#define HWs  3136
#define Gg   16
#define CGc  16
#define Mf   200704.0f
#define EPSf 1e-3f
#define NACC 152       // 16 sums + 136 upper-tri products
#define SBLK 9         // hw-chunks per group in k_stats
#define CHUNK 22304    // ceil(200704/9) rounded to multiple of 4

// Scratch (static device globals — no allocation)
__device__ float g_part[Gg][SBLK][NACC];
__device__ float g_A2[Gg][16][16][2];       // weight*wm, duplicated for f32x2
__device__ float g_beta2[Gg][16][2];        // bias - A*mean, duplicated

typedef unsigned long long u64;

__device__ __forceinline__ u64 fma2(u64 a, u64 b, u64 c) {
    u64 d;
    asm("fma.rn.f32x2 %0, %1, %2, %3;" : "=l"(d) : "l"(a), "l"(b), "l"(c));
    return d;
}

// ---------------------------------------------------------------------------
// Kernel 1: per-group channel sums + Gram partials. Grid (16, SBLK), 256 thr.
// float4 loads (16 LDG.128 per iter) so compute fully hides DRAM latency.
// ---------------------------------------------------------------------------
__global__ __launch_bounds__(256, 1) void k_stats(const float* __restrict__ X) {
    const int g = blockIdx.x, b = blockIdx.y;
    const int start = b * CHUNK;
    const int end   = (start + CHUNK < Nn * HWs) ? (start + CHUNK) : (Nn * HWs);
    const float* gbase = X + (size_t)g * CGc * HWs;

    float s[16];
    float p[136];
#pragma unroll
    for (int i = 0; i < 16; i++) s[i] = 0.f;
#pragma unroll
    for (int i = 0; i < 136; i++) p[i] = 0.f;

    for (int ppos = start + 4 * threadIdx.x; ppos < end; ppos += 1024) {
        const int n  = ppos / HWs;
        const int hw = ppos - n * HWs;                 // multiple of 4, never straddles a row
        const float* rowb = gbase + (size_t)n * Cc * HWs + hw;

        float4 v[16];
#pragma unroll
        for (int c = 0; c < 16; c++)
            v[c] = *(const float4*)(rowb + c * HWs);

#pragma unroll
        for (int c = 0; c < 16; c++)
            s[c] += (v[c].x + v[c].y) + (v[c].z + v[c].w);

        int idx = 0;
#pragma unroll
        for (int i = 0; i < 16; i++)
#pragma unroll
            for (int j = i; j < 16; j++) {
                float a = p[idx];
                a = fmaf(v[i].x, v[j].x, a);
                a = fmaf(v[i].y, v[j].y, a);
                a = fmaf(v[i].z, v[j].z, a);
                a = fmaf(v[i].w, v[j].w, a);
                p[idx] = a;
                idx++;
            }
    }

    // intra-warp tree reduction
#pragma unroll
    for (int off = 16; off > 0; off >>= 1) {
#pragma unroll
        for (int i = 0; i < 16; i++)  s[i] += __shfl_down_sync(0xffffffffu, s[i], off);
#pragma unroll
        for (int i = 0; i < 136; i++) p[i] += __shfl_down_sync(0xffffffffu, p[i], off);
    }

    __shared__ float red[8][NACC];
    const int warp = threadIdx.x >> 5, lane = threadIdx.x & 31;
    if (lane == 0) {
#pragma unroll
        for (int i = 0; i < 16; i++)  red[warp][i]      = s[i];
#pragma unroll
        for (int i = 0; i < 136; i++) red[warp][16 + i] = p[i];
    }
    __syncthreads();
    for (int t = threadIdx.x; t < NACC; t += 256) {
        float a = 0.f;
#pragma unroll
        for (int w = 0; w < 8; w++) a += red[w][t];
        g_part[g][b][t] = a;
    }
}

// ---------------------------------------------------------------------------
// Kernel 2: reduce partials -> sigma -> Newton-Schulz Sigma^{-1/2} -> fold
// weight/bias/mean into A = w*wm, beta = b - A*mean. 16 blocks x 256 threads.
// ---------------------------------------------------------------------------
__global__ __launch_bounds__(256, 1) void k_wm(const float* __restrict__ wgt,
                                               const float* __restrict__ bia) {
    const int g = blockIdx.x;
    const int t = threadIdx.x;

    __shared__ float S[NACC];
    __shared__ float meanS[16];
    __shared__ float sig[16][17], P[16][17], T1[16][17], T2[16][17];

    if (t < NACC) {
        float a = 0.f;
#pragma unroll
        for (int ch = 0; ch < SBLK; ch++) a += g_part[g][ch][t];
        S[t] = a;
    }
    __syncthreads();
    if (t < 16) meanS[t] = S[t] * (1.0f / Mf);
    __syncthreads();

    const int r = t >> 4, c = t & 15;
    const int i = (r < c) ? r : c;
    const int j = (r < c) ? c : r;
    const int pidx = 16 + i * 16 - (i * (i - 1)) / 2 + (j - i);
    float sv = S[pidx] * (1.0f / Mf) - meanS[r] * meanS[c] + ((r == c) ? EPSf : 0.f);
    sig[r][c] = sv;
    __syncthreads();

    float tr = 0.f;
#pragma unroll
    for (int k = 0; k < 16; k++) tr += sig[k][k];
    __syncthreads();

    sig[r][c] = sv / tr;                 // Sigma_N
    P[r][c] = (r == c) ? 1.f : 0.f;
    __syncthreads();

    for (int it = 0; it < 10; it++) {
        float d1 = 0.f;
#pragma unroll
        for (int k = 0; k < 16; k++) d1 += P[r][k] * P[k][c];
        T1[r][c] = d1;
        __syncthreads();
        float d2 = 0.f;
#pragma unroll
        for (int k = 0; k < 16; k++) d2 += T1[r][k] * P[k][c];
        T2[r][c] = d2;
        __syncthreads();
        float d3 = 0.f;
#pragma unroll
        for (int k = 0; k < 16; k++) d3 += T2[r][k] * sig[k][c];
        P[r][c] = 1.5f * P[r][c] - 0.5f * d3;
        __syncthreads();
    }

    const float wmv = P[r][c] * rsqrtf(tr);      // Sigma^{-1/2}
    const float Av  = wgt[g * 16 + r] * wmv;
    g_A2[g][r][c][0] = Av;
    g_A2[g][r][c][1] = Av;
    T1[r][c] = Av * meanS[c];
    __syncthreads();
    if (t < 16) {
        float acc = bia[g * 16 + t];
#pragma unroll
        for (int d = 0; d < 16; d++) acc -= T1[t][d];
        g_beta2[g][t][0] = acc;
        g_beta2[g][t][1] = acc;
    }
}

// ---------------------------------------------------------------------------
// Kernel 3: apply out = A*v + beta. Accumulator-outer f32x2 form:
// 32 u64 accumulators in regs, per-d one LDG.128 + 16 broadcast LDS + 32 FFMA2.
// ~85 regs -> occupancy 2, no spills. Grid (16, 64), 256 threads.
// ---------------------------------------------------------------------------
__global__ __launch_bounds__(256, 2) void k_apply(const float* __restrict__ X,
                                                  float* __restrict__ Y) {
    const int g = blockIdx.x, n = blockIdx.y;
    const int t = threadIdx.x;

    __shared__ u64 As[256];
    __shared__ u64 Bs[16];
    As[t] = ((const u64*)g_A2)[g * 256 + t];
    if (t < 16) Bs[t] = ((const u64*)g_beta2)[g * 16 + t];
    __syncthreads();

    const size_t off = ((size_t)n * Cc + (size_t)g * CGc) * HWs;
    const ulonglong2* xb = (const ulonglong2*)(X + off);
    ulonglong2*       yb = (ulonglong2*)(Y + off);
    const int HW4 = HWs / 4;   // 784 ulonglong2 (4 floats) per channel

    for (int q = t; q < HW4; q += 256) {
        u64 acc0[16], acc1[16];
#pragma unroll
        for (int c = 0; c < 16; c++) { acc0[c] = Bs[c]; acc1[c] = Bs[c]; }

#pragma unroll
        for (int d = 0; d < 16; d++) {
            const ulonglong2 xv = xb[d * HW4 + q];
#pragma unroll
            for (int c = 0; c < 16; c++) {
                const u64 w = As[c * 16 + d];
                acc0[c] = fma2(w, xv.x, acc0[c]);
                acc1[c] = fma2(w, xv.y, acc1[c]);
            }
        }
#pragma unroll
        for (int c = 0; c < 16; c++) {
            ulonglong2 o; o.x = acc0[c]; o.y = acc1[c];
            yb[c * HW4 + q] = o;
        }
    }
}

// ---------------------------------------------------------------------------
extern "C" void kernel_launch(void* const* d_in, const int* in_sizes, int n_in,
                              void* d_out, int out_size) {
    const float* X = (const float*)d_in[0];
    const float* W = (const float*)d_in[1];
    const float* B = (const float*)d_in[2];
    float* Y = (float*)d_out;

    k_stats<<<dim3(Gg, SBLK), 256>>>(X);
    k_wm<<<Gg, 256>>>(W, B);
    k_apply<<<dim3(Gg, Nn), 256>>>(X, Y);
}

// round 3
// speedup vs baseline: 2.7964x; 1.6124x over previous
#include <cuda_runtime.h>

#define Nn   64
#define Cc   256
#define HWs  3136
#define Gg   16
#define CGc  16
#define Mf   200704.0f
#define EPSf 1e-3f
#define NACC 152       // 16 sums + 136 upper-tri products
#define SBLK 9         // hw-chunks per group in k_stats
#define CHUNK 22304    // ceil(200704/9) rounded to multiple of 4

// Scratch (static device globals — no allocation)
__device__ float g_part[Gg][SBLK][NACC];
__device__ float g_A[Gg][16][16];           // weight * wm
__device__ float g_beta[Gg][16];            // bias - A*mean

// ---------------------------------------------------------------------------
// Kernel 1: per-group channel sums + Gram partials. Grid (16, SBLK), 256 thr.
// ---------------------------------------------------------------------------
__global__ __launch_bounds__(256, 1) void k_stats(const float* __restrict__ X) {
    const int g = blockIdx.x, b = blockIdx.y;
    const int start = b * CHUNK;
    const int end   = (start + CHUNK < Nn * HWs) ? (start + CHUNK) : (Nn * HWs);
    const float* gbase = X + (size_t)g * CGc * HWs;

    float s[16];
    float p[136];
#pragma unroll
    for (int i = 0; i < 16; i++) s[i] = 0.f;
#pragma unroll
    for (int i = 0; i < 136; i++) p[i] = 0.f;

    for (int ppos = start + 4 * threadIdx.x; ppos < end; ppos += 1024) {
        const int n  = ppos / HWs;
        const int hw = ppos - n * HWs;                 // multiple of 4, never straddles a row
        const float* rowb = gbase + (size_t)n * Cc * HWs + hw;

        float4 v[16];
#pragma unroll
        for (int c = 0; c < 16; c++)
            v[c] = *(const float4*)(rowb + c * HWs);

#pragma unroll
        for (int c = 0; c < 16; c++)
            s[c] += (v[c].x + v[c].y) + (v[c].z + v[c].w);

        int idx = 0;
#pragma unroll
        for (int i = 0; i < 16; i++)
#pragma unroll
            for (int j = i; j < 16; j++) {
                float a = p[idx];
                a = fmaf(v[i].x, v[j].x, a);
                a = fmaf(v[i].y, v[j].y, a);
                a = fmaf(v[i].z, v[j].z, a);
                a = fmaf(v[i].w, v[j].w, a);
                p[idx] = a;
                idx++;
            }
    }

    // intra-warp tree reduction
#pragma unroll
    for (int off = 16; off > 0; off >>= 1) {
#pragma unroll
        for (int i = 0; i < 16; i++)  s[i] += __shfl_down_sync(0xffffffffu, s[i], off);
#pragma unroll
        for (int i = 0; i < 136; i++) p[i] += __shfl_down_sync(0xffffffffu, p[i], off);
    }

    __shared__ float red[8][NACC];
    const int warp = threadIdx.x >> 5, lane = threadIdx.x & 31;
    if (lane == 0) {
#pragma unroll
        for (int i = 0; i < 16; i++)  red[warp][i]      = s[i];
#pragma unroll
        for (int i = 0; i < 136; i++) red[warp][16 + i] = p[i];
    }
    __syncthreads();
    for (int t = threadIdx.x; t < NACC; t += 256) {
        float a = 0.f;
#pragma unroll
        for (int w = 0; w < 8; w++) a += red[w][t];
        g_part[g][b][t] = a;
    }
}

// ---------------------------------------------------------------------------
// Kernel 2: reduce partials -> sigma -> Newton-Schulz Sigma^{-1/2} -> fold
// weight/bias/mean into A = w*wm, beta = b - A*mean. 16 blocks x 256 threads.
// ---------------------------------------------------------------------------
__global__ __launch_bounds__(256, 1) void k_wm(const float* __restrict__ wgt,
                                               const float* __restrict__ bia) {
    const int g = blockIdx.x;
    const int t = threadIdx.x;

    __shared__ float S[NACC];
    __shared__ float meanS[16];
    __shared__ float sig[16][17], P[16][17], T1[16][17], T2[16][17];

    if (t < NACC) {
        float a = 0.f;
#pragma unroll
        for (int ch = 0; ch < SBLK; ch++) a += g_part[g][ch][t];
        S[t] = a;
    }
    __syncthreads();
    if (t < 16) meanS[t] = S[t] * (1.0f / Mf);
    __syncthreads();

    const int r = t >> 4, c = t & 15;
    const int i = (r < c) ? r : c;
    const int j = (r < c) ? c : r;
    const int pidx = 16 + i * 16 - (i * (i - 1)) / 2 + (j - i);
    float sv = S[pidx] * (1.0f / Mf) - meanS[r] * meanS[c] + ((r == c) ? EPSf : 0.f);
    sig[r][c] = sv;
    __syncthreads();

    float tr = 0.f;
#pragma unroll
    for (int k = 0; k < 16; k++) tr += sig[k][k];
    __syncthreads();

    sig[r][c] = sv / tr;                 // Sigma_N
    P[r][c] = (r == c) ? 1.f : 0.f;
    __syncthreads();

    for (int it = 0; it < 10; it++) {
        float d1 = 0.f;
#pragma unroll
        for (int k = 0; k < 16; k++) d1 += P[r][k] * P[k][c];
        T1[r][c] = d1;
        __syncthreads();
        float d2 = 0.f;
#pragma unroll
        for (int k = 0; k < 16; k++) d2 += T1[r][k] * P[k][c];
        T2[r][c] = d2;
        __syncthreads();
        float d3 = 0.f;
#pragma unroll
        for (int k = 0; k < 16; k++) d3 += T2[r][k] * sig[k][c];
        P[r][c] = 1.5f * P[r][c] - 0.5f * d3;
        __syncthreads();
    }

    const float wmv = P[r][c] * rsqrtf(tr);      // Sigma^{-1/2}
    const float Av  = wgt[g * 16 + r] * wmv;
    g_A[g][r][c] = Av;
    T1[r][c] = Av * meanS[c];
    __syncthreads();
    if (t < 16) {
        float acc = bia[g * 16 + t];
#pragma unroll
        for (int d = 0; d < 16; d++) acc -= T1[t][d];
        g_beta[g][t] = acc;
    }
}

// ---------------------------------------------------------------------------
// Kernel 3: apply out = A*v + beta. Pure scalar fmaf / float4, NO inline asm,
// NO u64. 16 float4 accumulators (64 regs), beta hoisted to regs, weights as
// LDS.32 broadcasts. Grid (16, 64), 256 threads, occupancy 2.
// ---------------------------------------------------------------------------
__global__ __launch_bounds__(256, 2) void k_apply(const float* __restrict__ X,
                                                  float* __restrict__ Y) {
    const int g = blockIdx.x, n = blockIdx.y;
    const int t = threadIdx.x;

    __shared__ float As[256];     // A[c][d] flat
    __shared__ float BsS[16];
    As[t] = ((const float*)g_A)[g * 256 + t];
    if (t < 16) BsS[t] = g_beta[g][t];
    __syncthreads();

    float bb[16];
#pragma unroll
    for (int c = 0; c < 16; c++) bb[c] = BsS[c];

    const size_t off = ((size_t)n * Cc + (size_t)g * CGc) * HWs;
    const float4* xb = (const float4*)(X + off);
    float4*       yb = (float4*)(Y + off);
    const int HW4 = HWs / 4;   // 784 float4 per channel

    for (int q = t; q < HW4; q += 256) {
        float4 acc[16];
#pragma unroll
        for (int c = 0; c < 16; c++) {
            acc[c].x = bb[c]; acc[c].y = bb[c];
            acc[c].z = bb[c]; acc[c].w = bb[c];
        }

#pragma unroll
        for (int d = 0; d < 16; d++) {
            const float4 xv = xb[d * HW4 + q];
#pragma unroll
            for (int c = 0; c < 16; c++) {
                const float w = As[c * 16 + d];
                acc[c].x = fmaf(w, xv.x, acc[c].x);
                acc[c].y = fmaf(w, xv.y, acc[c].y);
                acc[c].z = fmaf(w, xv.z, acc[c].z);
                acc[c].w = fmaf(w, xv.w, acc[c].w);
            }
        }
#pragma unroll
        for (int c = 0; c < 16; c++)
            yb[c * HW4 + q] = acc[c];
    }
}

// ---------------------------------------------------------------------------
extern "C" void kernel_launch(void* const* d_in, const int* in_sizes, int n_in,
                              void* d_out, int out_size) {
    const float* X = (const float*)d_in[0];
    const float* W = (const float*)d_in[1];
    const float* B = (const float*)d_in[2];
    float* Y = (float*)d_out;

    k_stats<<<dim3(Gg, SBLK), 256>>>(X);
    k_wm<<<Gg, 256>>>(W, B);
    k_apply<<<dim3(Gg, Nn), 256>>>(X, Y);
}

// round 4
// speedup vs baseline: 6.3306x; 2.2639x over previous
#include <cuda_runtime.h>

#define Nn   64
#define Cc   256
#define HWs  3136
#define Gg   16
#define CGc  16
#define Mf   200704.0f
#define EPSf 1e-3f
#define NACC 152       // 16 sums + 136 upper-tri products
#define SBLK 9         // hw-chunks per group in k_stats
#define CHUNK 22304    // ceil(200704/9) rounded to multiple of 4

#define HW4       784            // float4 columns per (n, channel) row
#define TOT_TASKS (Nn * Gg * HW4)   // 802816 float4-column tasks
#define APPLY_BLOCKS 296         // 148 SMs x occupancy 2 = exactly one wave

// Scratch (static device globals — no allocation)
__device__ float g_part[Gg][SBLK][NACC];
__device__ float g_A[Gg][16][16];           // weight * wm   (A[g][c][d])
__device__ float g_beta[Gg][16];            // bias - A*mean

// ---------------------------------------------------------------------------
// Kernel 1: per-group channel sums + Gram partials. Grid (16, SBLK), 256 thr.
// ---------------------------------------------------------------------------
__global__ __launch_bounds__(256, 1) void k_stats(const float* __restrict__ X) {
    const int g = blockIdx.x, b = blockIdx.y;
    const int start = b * CHUNK;
    const int end   = (start + CHUNK < Nn * HWs) ? (start + CHUNK) : (Nn * HWs);
    const float* gbase = X + (size_t)g * CGc * HWs;

    float s[16];
    float p[136];
#pragma unroll
    for (int i = 0; i < 16; i++) s[i] = 0.f;
#pragma unroll
    for (int i = 0; i < 136; i++) p[i] = 0.f;

    for (int ppos = start + 4 * threadIdx.x; ppos < end; ppos += 1024) {
        const int n  = ppos / HWs;
        const int hw = ppos - n * HWs;                 // multiple of 4, never straddles a row
        const float* rowb = gbase + (size_t)n * Cc * HWs + hw;

        float4 v[16];
#pragma unroll
        for (int c = 0; c < 16; c++)
            v[c] = *(const float4*)(rowb + c * HWs);

#pragma unroll
        for (int c = 0; c < 16; c++)
            s[c] += (v[c].x + v[c].y) + (v[c].z + v[c].w);

        int idx = 0;
#pragma unroll
        for (int i = 0; i < 16; i++)
#pragma unroll
            for (int j = i; j < 16; j++) {
                float a = p[idx];
                a = fmaf(v[i].x, v[j].x, a);
                a = fmaf(v[i].y, v[j].y, a);
                a = fmaf(v[i].z, v[j].z, a);
                a = fmaf(v[i].w, v[j].w, a);
                p[idx] = a;
                idx++;
            }
    }

    // intra-warp tree reduction
#pragma unroll
    for (int off = 16; off > 0; off >>= 1) {
#pragma unroll
        for (int i = 0; i < 16; i++)  s[i] += __shfl_down_sync(0xffffffffu, s[i], off);
#pragma unroll
        for (int i = 0; i < 136; i++) p[i] += __shfl_down_sync(0xffffffffu, p[i], off);
    }

    __shared__ float red[8][NACC];
    const int warp = threadIdx.x >> 5, lane = threadIdx.x & 31;
    if (lane == 0) {
#pragma unroll
        for (int i = 0; i < 16; i++)  red[warp][i]      = s[i];
#pragma unroll
        for (int i = 0; i < 136; i++) red[warp][16 + i] = p[i];
    }
    __syncthreads();
    for (int t = threadIdx.x; t < NACC; t += 256) {
        float a = 0.f;
#pragma unroll
        for (int w = 0; w < 8; w++) a += red[w][t];
        g_part[g][b][t] = a;
    }
}

// ---------------------------------------------------------------------------
// Kernel 2: reduce partials -> sigma -> Newton-Schulz Sigma^{-1/2} -> fold
// weight/bias/mean into A = w*wm, beta = b - A*mean. 16 blocks x 256 threads.
// ---------------------------------------------------------------------------
__global__ __launch_bounds__(256, 1) void k_wm(const float* __restrict__ wgt,
                                               const float* __restrict__ bia) {
    const int g = blockIdx.x;
    const int t = threadIdx.x;

    __shared__ float S[NACC];
    __shared__ float meanS[16];
    __shared__ float sig[16][17], P[16][17], T1[16][17], T2[16][17];

    if (t < NACC) {
        float a = 0.f;
#pragma unroll
        for (int ch = 0; ch < SBLK; ch++) a += g_part[g][ch][t];
        S[t] = a;
    }
    __syncthreads();
    if (t < 16) meanS[t] = S[t] * (1.0f / Mf);
    __syncthreads();

    const int r = t >> 4, c = t & 15;
    const int i = (r < c) ? r : c;
    const int j = (r < c) ? c : r;
    const int pidx = 16 + i * 16 - (i * (i - 1)) / 2 + (j - i);
    float sv = S[pidx] * (1.0f / Mf) - meanS[r] * meanS[c] + ((r == c) ? EPSf : 0.f);
    sig[r][c] = sv;
    __syncthreads();

    float tr = 0.f;
#pragma unroll
    for (int k = 0; k < 16; k++) tr += sig[k][k];
    __syncthreads();

    sig[r][c] = sv / tr;                 // Sigma_N
    P[r][c] = (r == c) ? 1.f : 0.f;
    __syncthreads();

    for (int it = 0; it < 10; it++) {
        float d1 = 0.f;
#pragma unroll
        for (int k = 0; k < 16; k++) d1 += P[r][k] * P[k][c];
        T1[r][c] = d1;
        __syncthreads();
        float d2 = 0.f;
#pragma unroll
        for (int k = 0; k < 16; k++) d2 += T1[r][k] * P[k][c];
        T2[r][c] = d2;
        __syncthreads();
        float d3 = 0.f;
#pragma unroll
        for (int k = 0; k < 16; k++) d3 += T2[r][k] * sig[k][c];
        P[r][c] = 1.5f * P[r][c] - 0.5f * d3;
        __syncthreads();
    }

    const float wmv = P[r][c] * rsqrtf(tr);      // Sigma^{-1/2}
    const float Av  = wgt[g * 16 + r] * wmv;
    g_A[g][r][c] = Av;
    T1[r][c] = Av * meanS[c];
    __syncthreads();
    if (t < 16) {
        float acc = bia[g * 16 + t];
#pragma unroll
        for (int d = 0; d < 16; d++) acc -= T1[t][d];
        g_beta[g][t] = acc;
    }
}

// ---------------------------------------------------------------------------
// Kernel 3: apply out = A*v + beta. Persistent single-wave grid (296 blocks),
// all 16 groups' A/beta in smem, flat task index over all float4 columns.
// Perfect load balance (<=1 extra iter per thread), deep per-thread loops.
// ---------------------------------------------------------------------------
__global__ __launch_bounds__(256, 2) void k_apply(const float* __restrict__ X,
                                                  float* __restrict__ Y) {
    __shared__ float As[Gg * 256];   // As[g*256 + c*16 + d]
    __shared__ float Bs[Gg * 16];    // Bs[g*16 + c]

    for (int i = threadIdx.x; i < Gg * 256; i += 256)
        As[i] = ((const float*)g_A)[i];
    Bs[threadIdx.x] = ((const float*)g_beta)[threadIdx.x];
    __syncthreads();

    const int stride = APPLY_BLOCKS * 256;
    for (int t = blockIdx.x * 256 + threadIdx.x; t < TOT_TASKS; t += stride) {
        const int col = t / HW4;          // n*16 + g
        const int q   = t - col * HW4;    // hw4
        const int g   = col & 15;
        const int n   = col >> 4;

        const size_t off = ((size_t)n * Cc + (size_t)g * CGc) * HWs;
        const float4* xb = (const float4*)(X + off) + q;
        float4*       yb = (float4*)(Y + off) + q;
        const float*  Ag = As + g * 256;
        const float*  Bg = Bs + g * 16;

        float4 acc[16];
#pragma unroll
        for (int c = 0; c < 16; c++) {
            const float b = Bg[c];
            acc[c].x = b; acc[c].y = b; acc[c].z = b; acc[c].w = b;
        }

#pragma unroll
        for (int d = 0; d < 16; d++) {
            const float4 xv = xb[d * HW4];
#pragma unroll
            for (int c = 0; c < 16; c++) {
                const float w = Ag[c * 16 + d];
                acc[c].x = fmaf(w, xv.x, acc[c].x);
                acc[c].y = fmaf(w, xv.y, acc[c].y);
                acc[c].z = fmaf(w, xv.z, acc[c].z);
                acc[c].w = fmaf(w, xv.w, acc[c].w);
            }
        }
#pragma unroll
        for (int c = 0; c < 16; c++)
            yb[c * HW4] = acc[c];
    }
}

// ---------------------------------------------------------------------------
extern "C" void kernel_launch(void* const* d_in, const int* in_sizes, int n_in,
                              void* d_out, int out_size) {
    const float* X = (const float*)d_in[0];
    const float* W = (const float*)d_in[1];
    const float* B = (const float*)d_in[2];
    float* Y = (float*)d_out;

    k_stats<<<dim3(Gg, SBLK), 256>>>(X);
    k_wm<<<Gg, 256>>>(W, B);
    k_apply<<<APPLY_BLOCKS, 256>>>(X, Y);
}